// round 3
// baseline (speedup 1.0000x reference)
#include <cuda_runtime.h>

#define M_ROWS 65536     // B*T
#define KDIM   512       // H
#define NDIM   640       // G*V
#define GV     640
#define VPG    320
#define DPG    128
#define RPB    32                    // rows per block in fused kernel
#define NBLK   (M_ROWS / RPB)        // 2048

// Scratch (device globals: allocation-free per harness rules)
__device__ float g_logits[(size_t)M_ROWS * NDIM];   // 160 MB
__device__ float g_partial[(size_t)NBLK * GV];      // 5.2 MB  per-block soft-marginal partials
__device__ float g_marginal[GV];

// ---------------------------------------------------------------------------
// K1: SGEMM  logits[M,640] = hs[M,512] @ W[512,640] + bias
// 64x64 tile, 16-wide k-slab, 256 threads, 4x4 microtile.
// ---------------------------------------------------------------------------
__global__ void gemm_k(const float* __restrict__ A,
                       const float* __restrict__ W,
                       const float* __restrict__ bias) {
    __shared__ float As[16][64];
    __shared__ float Ws[16][64];
    const int bn = blockIdx.x * 64;     // N fastest -> concurrent blocks share A tile in L2
    const int bm = blockIdx.y * 64;
    const int tid = threadIdx.x;
    const int tx = tid & 15, ty = tid >> 4;
    float acc[4][4] = {};

    for (int k0 = 0; k0 < KDIM; k0 += 16) {
        {   // A tile: 64x16, one float4 per thread, store transposed
            int r = tid >> 2, c4 = (tid & 3) << 2;
            float4 v = *(const float4*)&A[(size_t)(bm + r) * KDIM + k0 + c4];
            As[c4 + 0][r] = v.x; As[c4 + 1][r] = v.y;
            As[c4 + 2][r] = v.z; As[c4 + 3][r] = v.w;
        }
        {   // W tile: 16x64, one float4 per thread
            int r = tid >> 4, c4 = (tid & 15) << 2;
            *(float4*)&Ws[r][c4] = *(const float4*)&W[(size_t)(k0 + r) * NDIM + bn + c4];
        }
        __syncthreads();
        #pragma unroll
        for (int kk = 0; kk < 16; kk++) {
            float a[4], b[4];
            *(float4*)a = *(float4*)&As[kk][ty * 4];
            *(float4*)b = *(float4*)&Ws[kk][tx * 4];
            #pragma unroll
            for (int i = 0; i < 4; i++)
                #pragma unroll
                for (int j = 0; j < 4; j++)
                    acc[i][j] = fmaf(a[i], b[j], acc[i][j]);
        }
        __syncthreads();
    }
    float4 bv = *(const float4*)&bias[bn + tx * 4];
    #pragma unroll
    for (int i = 0; i < 4; i++) {
        float4 o;
        o.x = acc[i][0] + bv.x; o.y = acc[i][1] + bv.y;
        o.z = acc[i][2] + bv.z; o.w = acc[i][3] + bv.w;
        *(float4*)&g_logits[(size_t)(bm + ty * 4 + i) * NDIM + bn + tx * 4] = o;
    }
}

// ---------------------------------------------------------------------------
// K2: fused gumbel-softmax + soft-marginal partial + codebook einsum.
// One block = 32 rows, 256 threads (8 warps). Dynamic smem: probs[32][640].
// ---------------------------------------------------------------------------
__global__ void fused_k(const float* __restrict__ gumbels,
                        const float* __restrict__ cb,
                        const int* __restrict__ mask,
                        float* __restrict__ out) {
    extern __shared__ float probs[];          // [RPB][GV] row-major, 80 KB
    __shared__ float sm_m2[RPB * 2];
    __shared__ float sm_s2inv[RPB * 2];
    __shared__ float sm_mask[RPB];

    const int tid  = threadIdx.x;
    const int lane = tid & 31;
    const int warp = tid >> 5;
    const int r0   = blockIdx.x * RPB;

    if (tid < RPB) sm_mask[tid] = mask[r0 + tid] ? 1.0f : 0.0f;

    // ---- P1: per (row, group) softmax stats + gumbel probs ----
    for (int p = warp; p < RPB * 2; p += 8) {
        const int r = p >> 1, g = p & 1;
        const float* lrow = &g_logits[(size_t)(r0 + r) * NDIM + g * VPG];
        const float* grow = &gumbels [(size_t)(r0 + r) * NDIM + g * VPG];
        float l[10], x1[10];
        float m1 = -1e30f, m2 = -1e30f;
        #pragma unroll
        for (int j = 0; j < 10; j++) {
            const int v = lane + j * 32;
            l[j]  = lrow[v];
            x1[j] = (l[j] + grow[v]) * 0.5f;          // temperature = 2
            m1 = fmaxf(m1, x1[j]); m2 = fmaxf(m2, l[j]);
        }
        #pragma unroll
        for (int o = 16; o; o >>= 1) {
            m1 = fmaxf(m1, __shfl_xor_sync(0xffffffffu, m1, o));
            m2 = fmaxf(m2, __shfl_xor_sync(0xffffffffu, m2, o));
        }
        float e1[10], s1 = 0.f, s2 = 0.f;
        #pragma unroll
        for (int j = 0; j < 10; j++) {
            e1[j] = __expf(x1[j] - m1); s1 += e1[j];
            s2 += __expf(l[j] - m2);
        }
        #pragma unroll
        for (int o = 16; o; o >>= 1) {
            s1 += __shfl_xor_sync(0xffffffffu, s1, o);
            s2 += __shfl_xor_sync(0xffffffffu, s2, o);
        }
        const float inv1 = 1.0f / s1;
        #pragma unroll
        for (int j = 0; j < 10; j++)
            probs[r * GV + g * VPG + lane + j * 32] = e1[j] * inv1;
        if (lane == 0) { sm_m2[p] = m2; sm_s2inv[p] = 1.0f / s2; }
    }
    __syncthreads();

    // ---- P1b: deterministic per-column soft-dist accumulation ----
    for (int c = tid; c < GV; c += 256) {
        const int g = (c >= VPG);
        const float* lcol = &g_logits[(size_t)r0 * NDIM + c];
        float acc = 0.f;
        #pragma unroll 4
        for (int r = 0; r < RPB; r++) {
            acc += sm_mask[r] *
                   __expf(lcol[(size_t)r * NDIM] - sm_m2[r * 2 + g]) * sm_s2inv[r * 2 + g];
        }
        g_partial[(size_t)blockIdx.x * GV + c] = acc;
    }

    // ---- P2: cv[row, g, d] = sum_v probs[row, g, v] * cb[g, v, d] ----
    const int g = tid >> 7;              // 0 or 1
    const int d = tid & 127;
    const float* cbg = &cb[(size_t)g * VPG * DPG + d];
    const int pbase = g * VPG;
    float acc[RPB];
    #pragma unroll
    for (int r = 0; r < RPB; r++) acc[r] = 0.f;

    for (int v = 0; v < VPG; v += 4) {
        const float c0 = cbg[(size_t)(v + 0) * DPG];
        const float c1 = cbg[(size_t)(v + 1) * DPG];
        const float c2 = cbg[(size_t)(v + 2) * DPG];
        const float c3 = cbg[(size_t)(v + 3) * DPG];
        #pragma unroll
        for (int r = 0; r < RPB; r++) {
            float4 pv = *(float4*)&probs[r * GV + pbase + v];   // warp-broadcast
            acc[r] = fmaf(pv.w, c3, fmaf(pv.z, c2, fmaf(pv.y, c1, fmaf(pv.x, c0, acc[r]))));
        }
    }
    #pragma unroll
    for (int r = 0; r < RPB; r++)
        out[(size_t)(r0 + r) * 256 + g * 128 + d] = acc[r];
}

// ---------------------------------------------------------------------------
// K3a: reduce per-block marginal partials -> g_marginal[640] (fixed order)
// ---------------------------------------------------------------------------
__global__ void reduce_marginal_k() {
    const int lane = threadIdx.x & 31;
    const int warp = threadIdx.x >> 5;
    const int c = blockIdx.x * 32 + lane;
    float s = 0.f;
    for (int b = warp; b < NBLK; b += 8)
        s += g_partial[(size_t)b * GV + c];
    __shared__ float red[8][32];
    red[warp][lane] = s;
    __syncthreads();
    if (warp == 0) {
        float t = red[0][lane];
        #pragma unroll
        for (int i = 1; i < 8; i++) t += red[i][lane];
        g_marginal[c] = t;
    }
}

// ---------------------------------------------------------------------------
// K3b: mask count + entropy -> perplexity scalar at out[out_size-1]
// Double-precision accumulation (single block; cost is negligible).
// ---------------------------------------------------------------------------
__global__ void finalize_k(const int* __restrict__ mask,
                           float* __restrict__ out, int out_size) {
    __shared__ double red0[256], red1[256];
    __shared__ int    redi[256];
    const int tid = threadIdx.x;
    int cnt = 0;
    for (int i = tid; i < M_ROWS; i += 256) cnt += mask[i] ? 1 : 0;
    redi[tid] = cnt; __syncthreads();
    for (int o = 128; o; o >>= 1) { if (tid < o) redi[tid] += redi[tid + o]; __syncthreads(); }
    const double inv = 1.0 / (double)redi[0];

    double s0 = 0.0, s1 = 0.0;
    for (int c = tid; c < GV; c += 256) {
        const double m = (double)g_marginal[c] * inv;
        // match reference: log computed on (m + 1e-7) in fp32 semantics is fine;
        // double here only tightens the accumulation.
        const double t = m * log(m + 1e-7);
        if (c < VPG) s0 += t; else s1 += t;
    }
    red0[tid] = s0; red1[tid] = s1; __syncthreads();
    for (int o = 128; o; o >>= 1) {
        if (tid < o) { red0[tid] += red0[tid + o]; red1[tid] += red1[tid + o]; }
        __syncthreads();
    }
    if (tid == 0) out[out_size - 1] = (float)(exp(-red0[0]) + exp(-red1[0]));
}

// ---------------------------------------------------------------------------
extern "C" void kernel_launch(void* const* d_in, const int* in_sizes, int n_in,
                              void* d_out, int out_size) {
    const float* hs   = (const float*)d_in[0];   // [B,T,H]
    const float* gum  = (const float*)d_in[1];   // [B*T*G, V]
    const float* W    = (const float*)d_in[2];   // [H, G*V]
    const float* bias = (const float*)d_in[3];   // [G*V]
    const float* cb   = (const float*)d_in[4];   // [1, G*V, D/G]
    const int*   mask = (const int*)d_in[5];     // [B,T] bool -> int32 per harness marshaling
    float* out = (float*)d_out;

    cudaFuncSetAttribute(fused_k, cudaFuncAttributeMaxDynamicSharedMemorySize,
                         RPB * GV * (int)sizeof(float));

    gemm_k<<<dim3(NDIM / 64, M_ROWS / 64), 256>>>(hs, W, bias);
    fused_k<<<NBLK, 256, RPB * GV * (int)sizeof(float)>>>(gum, cb, mask, out);
    reduce_marginal_k<<<GV / 32, 256>>>();
    finalize_k<<<1, 256>>>(mask, out, out_size);
}

// round 8
// speedup vs baseline: 1.6964x; 1.6964x over previous
#include <cuda_runtime.h>
#include <cuda_bf16.h>
#include <cstdint>

#define M_ROWS 65536     // B*T
#define KDIM   512       // H
#define NDIM   640       // G*V
#define GV     640
#define VPG    320
#define DPG    128
#define RPB    32
#define NBLK   (M_ROWS / RPB)

// GEMM tiling
#define MT 128
#define NT 128
#define KC 32            // k-chunk in smem
#define NKC (KDIM / KC)  // 16
#define APAD 8
#define LDS_STRIDE (KC + APAD)   // 40 bf16 -> conflict-free frag loads

// Scratch (device globals: allocation-free per harness rules)
__device__ float g_logits[(size_t)M_ROWS * NDIM];            // 160 MB
__device__ float g_partial[(size_t)NBLK * GV];               // 5.2 MB
__device__ float g_marginal[GV];
__device__ unsigned short g_wt_hi[(size_t)NDIM * KDIM];      // W^T hi, [640][512] bf16 bits
__device__ unsigned short g_wt_lo[(size_t)NDIM * KDIM];      // W^T lo
__device__ unsigned short g_a_hi[(size_t)M_ROWS * KDIM];     // A hi, [65536][512]
__device__ unsigned short g_a_lo[(size_t)M_ROWS * KDIM];     // A lo

// ---------------------------------------------------------------------------
__device__ __forceinline__ void mma_bf16(float* c, const uint32_t* a, const uint32_t* b) {
    asm volatile(
        "mma.sync.aligned.m16n8k16.row.col.f32.bf16.bf16.f32 "
        "{%0,%1,%2,%3}, {%4,%5,%6,%7}, {%8,%9}, {%0,%1,%2,%3};"
        : "+f"(c[0]), "+f"(c[1]), "+f"(c[2]), "+f"(c[3])
        : "r"(a[0]), "r"(a[1]), "r"(a[2]), "r"(a[3]), "r"(b[0]), "r"(b[1]));
}

__device__ __forceinline__ unsigned short bf_hi(float x) {
    return __bfloat16_as_ushort(__float2bfloat16_rn(x));
}
__device__ __forceinline__ unsigned short bf_lo(float x, unsigned short h) {
    return __bfloat16_as_ushort(
        __float2bfloat16_rn(x - __bfloat162float(__ushort_as_bfloat16(h))));
}

// ---------------------------------------------------------------------------
// conv_w: W[512][640] fp32 -> W^T hi/lo bf16 [640][512]
// ---------------------------------------------------------------------------
__global__ void conv_w(const float* __restrict__ W) {
    int idx = blockIdx.x * 256 + threadIdx.x;
    if (idx >= NDIM * KDIM) return;
    int n = idx >> 9, k = idx & 511;
    float x = W[(size_t)k * NDIM + n];
    unsigned short h = bf_hi(x);
    g_wt_hi[idx] = h;
    g_wt_lo[idx] = bf_lo(x, h);
}

// ---------------------------------------------------------------------------
// conv_a: A fp32 -> hi/lo bf16 (same k-major layout), vectorized
// ---------------------------------------------------------------------------
__global__ void conv_a(const float* __restrict__ A) {
    size_t i = (size_t)blockIdx.x * 256 + threadIdx.x;   // float4 index
    float4 v = ((const float4*)A)[i];
    ushort4 h, l;
    h.x = bf_hi(v.x); l.x = bf_lo(v.x, h.x);
    h.y = bf_hi(v.y); l.y = bf_lo(v.y, h.y);
    h.z = bf_hi(v.z); l.z = bf_lo(v.z, h.z);
    h.w = bf_hi(v.w); l.w = bf_lo(v.w, h.w);
    ((ushort4*)g_a_hi)[i] = h;
    ((ushort4*)g_a_lo)[i] = l;
}

// ---------------------------------------------------------------------------
// mma_gemm: logits[M,640] = A @ W + bias via bf16-split mma.sync (3 passes).
// CTA 128x128, 256 threads = 8 warps (4 M x 2 N), warp tile 32x64.
// ---------------------------------------------------------------------------
__global__ void __launch_bounds__(256, 2)
mma_gemm(const float* __restrict__ bias) {
    __shared__ unsigned short Ahs[MT * LDS_STRIDE];
    __shared__ unsigned short Als[MT * LDS_STRIDE];
    __shared__ unsigned short Bhs[NT * LDS_STRIDE];
    __shared__ unsigned short Bls[NT * LDS_STRIDE];

    const int tid  = threadIdx.x;
    const int wid  = tid >> 5;
    const int lane = tid & 31;
    const int g    = lane >> 2;          // group id (0..7)
    const int t    = lane & 3;           // thread-in-group
    const int n0   = blockIdx.x * NT;
    const int m0   = blockIdx.y * MT;
    const int wm   = (wid & 3) * 32;     // warp m offset
    const int wn   = (wid >> 2) * 64;    // warp n offset

    float c[2][8][4];
    #pragma unroll
    for (int i = 0; i < 2; i++)
        #pragma unroll
        for (int j = 0; j < 8; j++)
            #pragma unroll
            for (int q = 0; q < 4; q++) c[i][j][q] = 0.f;

    for (int kc = 0; kc < NKC; ++kc) {
        __syncthreads();   // previous compute done before overwriting smem
        // load chunk: 4 matrices, each 128 rows x 32 bf16 (= 4 uint4/row)
        #pragma unroll
        for (int u = 0; u < 2; ++u) {
            const int idx = u * 256 + tid;     // 0..511
            const int r = idx >> 2, cc = idx & 3;
            const size_t ga = (size_t)(m0 + r) * KDIM + kc * KC + cc * 8;
            const size_t gb = (size_t)(n0 + r) * KDIM + kc * KC + cc * 8;
            const int so = r * LDS_STRIDE + cc * 8;
            *(uint4*)&Ahs[so] = *(const uint4*)&g_a_hi[ga];
            *(uint4*)&Als[so] = *(const uint4*)&g_a_lo[ga];
            *(uint4*)&Bhs[so] = *(const uint4*)&g_wt_hi[gb];
            *(uint4*)&Bls[so] = *(const uint4*)&g_wt_lo[gb];
        }
        __syncthreads();

        #pragma unroll
        for (int ks = 0; ks < 2; ++ks) {
            const int kb = ks * 16;
            uint32_t ah[2][4], al[2][4];
            #pragma unroll
            for (int i = 0; i < 2; ++i) {
                const int r = wm + i * 16 + g;
                const int o0 = r * LDS_STRIDE + kb + 2 * t;
                ah[i][0] = *(const uint32_t*)&Ahs[o0];
                ah[i][1] = *(const uint32_t*)&Ahs[o0 + 8 * LDS_STRIDE];
                ah[i][2] = *(const uint32_t*)&Ahs[o0 + 8];
                ah[i][3] = *(const uint32_t*)&Ahs[o0 + 8 * LDS_STRIDE + 8];
                al[i][0] = *(const uint32_t*)&Als[o0];
                al[i][1] = *(const uint32_t*)&Als[o0 + 8 * LDS_STRIDE];
                al[i][2] = *(const uint32_t*)&Als[o0 + 8];
                al[i][3] = *(const uint32_t*)&Als[o0 + 8 * LDS_STRIDE + 8];
            }
            #pragma unroll
            for (int j = 0; j < 8; ++j) {
                const int n = wn + j * 8 + g;
                const int o0 = n * LDS_STRIDE + kb + 2 * t;
                uint32_t bh[2], bl[2];
                bh[0] = *(const uint32_t*)&Bhs[o0];
                bh[1] = *(const uint32_t*)&Bhs[o0 + 8];
                bl[0] = *(const uint32_t*)&Bls[o0];
                bl[1] = *(const uint32_t*)&Bls[o0 + 8];
                #pragma unroll
                for (int i = 0; i < 2; ++i) {
                    mma_bf16(c[i][j], ah[i], bh);
                    mma_bf16(c[i][j], al[i], bh);
                    mma_bf16(c[i][j], ah[i], bl);
                }
            }
        }
    }

    // epilogue: add bias, store fp32 logits
    #pragma unroll
    for (int j = 0; j < 8; ++j) {
        const int col = n0 + wn + j * 8 + 2 * t;
        const float2 bv = *(const float2*)&bias[col];
        #pragma unroll
        for (int i = 0; i < 2; ++i) {
            const int row = m0 + wm + i * 16 + g;
            float2 v0 = { c[i][j][0] + bv.x, c[i][j][1] + bv.y };
            float2 v1 = { c[i][j][2] + bv.x, c[i][j][3] + bv.y };
            *(float2*)&g_logits[(size_t)row * NDIM + col]       = v0;
            *(float2*)&g_logits[(size_t)(row + 8) * NDIM + col] = v1;
        }
    }
}

// ---------------------------------------------------------------------------
// K2: fused gumbel-softmax + soft-marginal partial + codebook einsum
// ---------------------------------------------------------------------------
__global__ void fused_k(const float* __restrict__ gumbels,
                        const float* __restrict__ cb,
                        const int* __restrict__ mask,
                        float* __restrict__ out) {
    extern __shared__ float probs[];          // [RPB][GV], 80 KB
    __shared__ float sm_m2[RPB * 2];
    __shared__ float sm_s2inv[RPB * 2];
    __shared__ float sm_mask[RPB];

    const int tid  = threadIdx.x;
    const int lane = tid & 31;
    const int warp = tid >> 5;
    const int r0   = blockIdx.x * RPB;

    if (tid < RPB) sm_mask[tid] = mask[r0 + tid] ? 1.0f : 0.0f;

    for (int p = warp; p < RPB * 2; p += 8) {
        const int r = p >> 1, g = p & 1;
        const float* lrow = &g_logits[(size_t)(r0 + r) * NDIM + g * VPG];
        const float* grow = &gumbels [(size_t)(r0 + r) * NDIM + g * VPG];
        float l[10], x1[10];
        float m1 = -1e30f, m2 = -1e30f;
        #pragma unroll
        for (int j = 0; j < 10; j++) {
            const int v = lane + j * 32;
            l[j]  = lrow[v];
            x1[j] = (l[j] + grow[v]) * 0.5f;
            m1 = fmaxf(m1, x1[j]); m2 = fmaxf(m2, l[j]);
        }
        #pragma unroll
        for (int o = 16; o; o >>= 1) {
            m1 = fmaxf(m1, __shfl_xor_sync(0xffffffffu, m1, o));
            m2 = fmaxf(m2, __shfl_xor_sync(0xffffffffu, m2, o));
        }
        float e1[10], s1 = 0.f, s2 = 0.f;
        #pragma unroll
        for (int j = 0; j < 10; j++) {
            e1[j] = __expf(x1[j] - m1); s1 += e1[j];
            s2 += __expf(l[j] - m2);
        }
        #pragma unroll
        for (int o = 16; o; o >>= 1) {
            s1 += __shfl_xor_sync(0xffffffffu, s1, o);
            s2 += __shfl_xor_sync(0xffffffffu, s2, o);
        }
        const float inv1 = 1.0f / s1;
        #pragma unroll
        for (int j = 0; j < 10; j++)
            probs[r * GV + g * VPG + lane + j * 32] = e1[j] * inv1;
        if (lane == 0) { sm_m2[p] = m2; sm_s2inv[p] = 1.0f / s2; }
    }
    __syncthreads();

    for (int cix = tid; cix < GV; cix += 256) {
        const int g = (cix >= VPG);
        const float* lcol = &g_logits[(size_t)r0 * NDIM + cix];
        float acc = 0.f;
        #pragma unroll 4
        for (int r = 0; r < RPB; r++) {
            acc += sm_mask[r] *
                   __expf(lcol[(size_t)r * NDIM] - sm_m2[r * 2 + g]) * sm_s2inv[r * 2 + g];
        }
        g_partial[(size_t)blockIdx.x * GV + cix] = acc;
    }

    const int g = tid >> 7;
    const int d = tid & 127;
    const float* cbg = &cb[(size_t)g * VPG * DPG + d];
    const int pbase = g * VPG;
    float acc[RPB];
    #pragma unroll
    for (int r = 0; r < RPB; r++) acc[r] = 0.f;

    for (int v = 0; v < VPG; v += 4) {
        const float c0 = cbg[(size_t)(v + 0) * DPG];
        const float c1 = cbg[(size_t)(v + 1) * DPG];
        const float c2 = cbg[(size_t)(v + 2) * DPG];
        const float c3 = cbg[(size_t)(v + 3) * DPG];
        #pragma unroll
        for (int r = 0; r < RPB; r++) {
            float4 pv = *(float4*)&probs[r * GV + pbase + v];
            acc[r] = fmaf(pv.w, c3, fmaf(pv.z, c2, fmaf(pv.y, c1, fmaf(pv.x, c0, acc[r]))));
        }
    }
    #pragma unroll
    for (int r = 0; r < RPB; r++)
        out[(size_t)(r0 + r) * 256 + g * 128 + d] = acc[r];
}

// ---------------------------------------------------------------------------
__global__ void reduce_marginal_k() {
    const int lane = threadIdx.x & 31;
    const int warp = threadIdx.x >> 5;
    const int c = blockIdx.x * 32 + lane;
    float s = 0.f;
    for (int b = warp; b < NBLK; b += 8)
        s += g_partial[(size_t)b * GV + c];
    __shared__ float red[8][32];
    red[warp][lane] = s;
    __syncthreads();
    if (warp == 0) {
        float v = red[0][lane];
        #pragma unroll
        for (int i = 1; i < 8; i++) v += red[i][lane];
        g_marginal[c] = v;
    }
}

// ---------------------------------------------------------------------------
__global__ void finalize_k(const int* __restrict__ mask,
                           float* __restrict__ out, int out_size) {
    __shared__ double red0[1024], red1[1024];
    __shared__ int    redi[1024];
    const int tid = threadIdx.x;
    const int4* m4 = (const int4*)mask;
    int cnt = 0;
    for (int i = tid; i < M_ROWS / 4; i += 1024) {
        int4 v = m4[i];
        cnt += (v.x != 0) + (v.y != 0) + (v.z != 0) + (v.w != 0);
    }
    redi[tid] = cnt; __syncthreads();
    for (int o = 512; o; o >>= 1) { if (tid < o) redi[tid] += redi[tid + o]; __syncthreads(); }
    const double inv = 1.0 / (double)redi[0];

    double s0 = 0.0, s1 = 0.0;
    for (int c = tid; c < GV; c += 1024) {
        const double m = (double)g_marginal[c] * inv;
        const double tt = m * log(m + 1e-7);
        if (c < VPG) s0 += tt; else s1 += tt;
    }
    red0[tid] = s0; red1[tid] = s1; __syncthreads();
    for (int o = 512; o; o >>= 1) {
        if (tid < o) { red0[tid] += red0[tid + o]; red1[tid] += red1[tid + o]; }
        __syncthreads();
    }
    if (tid == 0) out[out_size - 1] = (float)(exp(-red0[0]) + exp(-red1[0]));
}

// ---------------------------------------------------------------------------
extern "C" void kernel_launch(void* const* d_in, const int* in_sizes, int n_in,
                              void* d_out, int out_size) {
    const float* hs   = (const float*)d_in[0];
    const float* gum  = (const float*)d_in[1];
    const float* W    = (const float*)d_in[2];
    const float* bias = (const float*)d_in[3];
    const float* cb   = (const float*)d_in[4];
    const int*   mask = (const int*)d_in[5];
    float* out = (float*)d_out;

    static int attr_done = 0;
    if (!attr_done) {
        cudaFuncSetAttribute(fused_k, cudaFuncAttributeMaxDynamicSharedMemorySize,
                             RPB * GV * (int)sizeof(float));
        attr_done = 1;
    }

    conv_w<<<(NDIM * KDIM + 255) / 256, 256>>>(W);
    conv_a<<<(M_ROWS * KDIM / 4) / 256, 256>>>(hs);
    mma_gemm<<<dim3(NDIM / NT, M_ROWS / MT), 256>>>(bias);
    fused_k<<<NBLK, 256, RPB * GV * (int)sizeof(float)>>>(gum, cb, mask, out);
    reduce_marginal_k<<<GV / 32, 256>>>();
    finalize_k<<<1, 1024>>>(mask, out, out_size);
}

// round 12
// speedup vs baseline: 1.9041x; 1.1224x over previous
#include <cuda_runtime.h>
#include <cuda_bf16.h>
#include <cstdint>

#define M_ROWS 65536     // B*T
#define KDIM   512       // H
#define NDIM   640       // G*V
#define GV     640
#define VPG    320
#define DPG    128
#define RPB    32
#define NBLK   (M_ROWS / RPB)

// GEMM tiling
#define MT 128
#define NT 128
#define KC 32
#define NKC (KDIM / KC)          // 16
#define APAD 8
#define LDS_STRIDE (KC + APAD)   // 40 ushorts
#define TILE_U   (MT * LDS_STRIDE)          // 5120 ushorts
#define STAGE_U  (4 * TILE_U)               // 20480 ushorts
#define TILE_B   (TILE_U * 2)               // 10240 bytes
#define STAGE_B  (STAGE_U * 2)              // 40960 bytes
#define SMEM_GEMM (2 * STAGE_B)             // 81920 bytes

// fused_k: transposed probs with pad
#define TPAD 34
#define SMEM_FUSED (GV * TPAD * 4)          // 87040 bytes

// Scratch (device globals: allocation-free per harness rules)
__device__ float g_logits[(size_t)M_ROWS * NDIM];            // 160 MB
__device__ float g_partial[(size_t)NBLK * GV];               // 5.2 MB
__device__ float g_marginal[GV];
__device__ unsigned short g_wt_hi[(size_t)NDIM * KDIM];      // W^T hi [640][512]
__device__ unsigned short g_wt_lo[(size_t)NDIM * KDIM];
__device__ unsigned short g_a_hi[(size_t)M_ROWS * KDIM];     // A hi [65536][512]
__device__ unsigned short g_a_lo[(size_t)M_ROWS * KDIM];

// ---------------------------------------------------------------------------
__device__ __forceinline__ void mma_bf16(float* c, const uint32_t* a, const uint32_t* b) {
    asm volatile(
        "mma.sync.aligned.m16n8k16.row.col.f32.bf16.bf16.f32 "
        "{%0,%1,%2,%3}, {%4,%5,%6,%7}, {%8,%9}, {%0,%1,%2,%3};"
        : "+f"(c[0]), "+f"(c[1]), "+f"(c[2]), "+f"(c[3])
        : "r"(a[0]), "r"(a[1]), "r"(a[2]), "r"(a[3]), "r"(b[0]), "r"(b[1]));
}
__device__ __forceinline__ unsigned short bf_hi(float x) {
    return __bfloat16_as_ushort(__float2bfloat16_rn(x));
}
__device__ __forceinline__ unsigned short bf_lo(float x, unsigned short h) {
    return __bfloat16_as_ushort(
        __float2bfloat16_rn(x - __bfloat162float(__ushort_as_bfloat16(h))));
}
__device__ __forceinline__ uint32_t smem_u32(const void* p) {
    uint32_t a;
    asm("{ .reg .u64 t; cvta.to.shared.u64 t, %1; cvt.u32.u64 %0, t; }" : "=r"(a) : "l"(p));
    return a;
}
__device__ __forceinline__ void cp_async16(uint32_t dst, const void* src) {
    asm volatile("cp.async.cg.shared.global [%0], [%1], 16;" :: "r"(dst), "l"(src));
}
#define CP_COMMIT() asm volatile("cp.async.commit_group;" ::: "memory")
#define CP_WAIT(n)  asm volatile("cp.async.wait_group %0;" :: "n"(n) : "memory")

__device__ __forceinline__ unsigned long long pack2(float x) {
    unsigned long long r;
    asm("mov.b64 %0, {%1,%2};" : "=l"(r) : "f"(x), "f"(x));
    return r;
}
__device__ __forceinline__ void ffma2(unsigned long long& d, unsigned long long a,
                                      unsigned long long b) {
    asm("fma.rn.f32x2 %0, %1, %2, %0;" : "+l"(d) : "l"(a), "l"(b));
}

// ---------------------------------------------------------------------------
__global__ void conv_w(const float* __restrict__ W) {
    int idx = blockIdx.x * 256 + threadIdx.x;
    if (idx >= NDIM * KDIM) return;
    int n = idx >> 9, k = idx & 511;
    float x = W[(size_t)k * NDIM + n];
    unsigned short h = bf_hi(x);
    g_wt_hi[idx] = h;
    g_wt_lo[idx] = bf_lo(x, h);
}

__global__ void conv_a(const float* __restrict__ A) {
    size_t i = (size_t)blockIdx.x * 256 + threadIdx.x;
    float4 v = ((const float4*)A)[i];
    ushort4 h, l;
    h.x = bf_hi(v.x); l.x = bf_lo(v.x, h.x);
    h.y = bf_hi(v.y); l.y = bf_lo(v.y, h.y);
    h.z = bf_hi(v.z); l.z = bf_lo(v.z, h.z);
    h.w = bf_hi(v.w); l.w = bf_lo(v.w, h.w);
    ((ushort4*)g_a_hi)[i] = h;
    ((ushort4*)g_a_lo)[i] = l;
}

// ---------------------------------------------------------------------------
// mma_gemm: cp.async double-buffered bf16-split mma.sync GEMM.
// ---------------------------------------------------------------------------
__device__ __forceinline__ void issue_loads(uint32_t sbase, int m0, int n0, int kc, int tid) {
    #pragma unroll
    for (int u = 0; u < 2; ++u) {
        const int idx = u * 256 + tid;                 // 0..511
        const int r = idx >> 2, cc = idx & 3;
        const size_t ga = (size_t)(m0 + r) * KDIM + kc * KC + cc * 8;
        const size_t gb = (size_t)(n0 + r) * KDIM + kc * KC + cc * 8;
        const uint32_t so = (uint32_t)(r * LDS_STRIDE + cc * 8) * 2;  // bytes
        cp_async16(sbase + so,              g_a_hi  + ga);
        cp_async16(sbase + TILE_B + so,     g_a_lo  + ga);
        cp_async16(sbase + 2 * TILE_B + so, g_wt_hi + gb);
        cp_async16(sbase + 3 * TILE_B + so, g_wt_lo + gb);
    }
}

__global__ void __launch_bounds__(256, 2)
mma_gemm(const float* __restrict__ bias) {
    extern __shared__ unsigned short smg[];
    const uint32_t sb = smem_u32(smg);

    const int tid  = threadIdx.x;
    const int wid  = tid >> 5;
    const int lane = tid & 31;
    const int g    = lane >> 2;
    const int t    = lane & 3;
    const int n0   = blockIdx.x * NT;
    const int m0   = blockIdx.y * MT;
    const int wm   = (wid & 3) * 32;
    const int wn   = (wid >> 2) * 64;

    float c[2][8][4];
    #pragma unroll
    for (int i = 0; i < 2; i++)
        #pragma unroll
        for (int j = 0; j < 8; j++)
            #pragma unroll
            for (int q = 0; q < 4; q++) c[i][j][q] = 0.f;

    issue_loads(sb, m0, n0, 0, tid);
    CP_COMMIT();

    for (int kc = 0; kc < NKC; ++kc) {
        if (kc + 1 < NKC) {
            issue_loads(sb + ((kc + 1) & 1) * STAGE_B, m0, n0, kc + 1, tid);
            CP_COMMIT();
            CP_WAIT(1);
        } else {
            CP_WAIT(0);
        }
        __syncthreads();

        const unsigned short* Ahs = smg + (kc & 1) * STAGE_U;
        const unsigned short* Als = Ahs + TILE_U;
        const unsigned short* Bhs = Ahs + 2 * TILE_U;
        const unsigned short* Bls = Ahs + 3 * TILE_U;

        #pragma unroll
        for (int ks = 0; ks < 2; ++ks) {
            const int kb = ks * 16;
            uint32_t ah[2][4], al[2][4];
            #pragma unroll
            for (int i = 0; i < 2; ++i) {
                const int r = wm + i * 16 + g;
                const int o0 = r * LDS_STRIDE + kb + 2 * t;
                ah[i][0] = *(const uint32_t*)&Ahs[o0];
                ah[i][1] = *(const uint32_t*)&Ahs[o0 + 8 * LDS_STRIDE];
                ah[i][2] = *(const uint32_t*)&Ahs[o0 + 8];
                ah[i][3] = *(const uint32_t*)&Ahs[o0 + 8 * LDS_STRIDE + 8];
                al[i][0] = *(const uint32_t*)&Als[o0];
                al[i][1] = *(const uint32_t*)&Als[o0 + 8 * LDS_STRIDE];
                al[i][2] = *(const uint32_t*)&Als[o0 + 8];
                al[i][3] = *(const uint32_t*)&Als[o0 + 8 * LDS_STRIDE + 8];
            }
            #pragma unroll
            for (int j = 0; j < 8; ++j) {
                const int n = wn + j * 8 + g;
                const int o0 = n * LDS_STRIDE + kb + 2 * t;
                uint32_t bh[2], bl[2];
                bh[0] = *(const uint32_t*)&Bhs[o0];
                bh[1] = *(const uint32_t*)&Bhs[o0 + 8];
                bl[0] = *(const uint32_t*)&Bls[o0];
                bl[1] = *(const uint32_t*)&Bls[o0 + 8];
                #pragma unroll
                for (int i = 0; i < 2; ++i) {
                    mma_bf16(c[i][j], ah[i], bh);
                    mma_bf16(c[i][j], al[i], bh);
                    mma_bf16(c[i][j], ah[i], bl);
                }
            }
        }
        __syncthreads();
    }

    #pragma unroll
    for (int j = 0; j < 8; ++j) {
        const int col = n0 + wn + j * 8 + 2 * t;
        const float2 bv = *(const float2*)&bias[col];
        #pragma unroll
        for (int i = 0; i < 2; ++i) {
            const int row = m0 + wm + i * 16 + g;
            float2 v0 = { c[i][j][0] + bv.x, c[i][j][1] + bv.y };
            float2 v1 = { c[i][j][2] + bv.x, c[i][j][3] + bv.y };
            *(float2*)&g_logits[(size_t)row * NDIM + col]       = v0;
            *(float2*)&g_logits[(size_t)(row + 8) * NDIM + col] = v1;
        }
    }
}

// ---------------------------------------------------------------------------
// fused_k: gumbel-softmax (transposed probs) + in-register soft-marginal +
//          FFMA2 codebook einsum.
// Dyn smem: probs_t[640][34] floats.
// ---------------------------------------------------------------------------
__global__ void fused_k(const float* __restrict__ gumbels,
                        const float* __restrict__ cb,
                        const int* __restrict__ mask,
                        float* __restrict__ out) {
    extern __shared__ float probs_t[];        // [GV][TPAD]
    __shared__ float wpart[8][VPG];
    __shared__ float sm_mask[RPB];

    const int tid  = threadIdx.x;
    const int lane = tid & 31;
    const int warp = tid >> 5;
    const int r0   = blockIdx.x * RPB;

    if (tid < RPB) sm_mask[tid] = mask[r0 + tid] ? 1.0f : 0.0f;
    __syncthreads();

    // ---- P1: per (row, group) softmaxes; warp owns group g = warp&1 ----
    const int g1    = warp & 1;
    const int rbase = warp >> 1;
    const int goff  = g1 * VPG;
    float macc[10];
    #pragma unroll
    for (int j = 0; j < 10; j++) macc[j] = 0.f;

    #pragma unroll 1
    for (int k = 0; k < 8; ++k) {
        const int r = rbase + 4 * k;
        const float* lrow = &g_logits[(size_t)(r0 + r) * NDIM + goff];
        const float* grow = &gumbels [(size_t)(r0 + r) * NDIM + goff];
        float l[10], x1[10];
        float m1 = -1e30f, m2 = -1e30f;
        #pragma unroll
        for (int j = 0; j < 10; j++) {
            const int v = lane + j * 32;
            l[j]  = lrow[v];
            x1[j] = (l[j] + grow[v]) * 0.5f;
            m1 = fmaxf(m1, x1[j]); m2 = fmaxf(m2, l[j]);
        }
        #pragma unroll
        for (int o = 16; o; o >>= 1) {
            m1 = fmaxf(m1, __shfl_xor_sync(0xffffffffu, m1, o));
            m2 = fmaxf(m2, __shfl_xor_sync(0xffffffffu, m2, o));
        }
        float e1[10], s1 = 0.f, s2 = 0.f;
        #pragma unroll
        for (int j = 0; j < 10; j++) {
            e1[j] = __expf(x1[j] - m1); s1 += e1[j];
            s2 += __expf(l[j] - m2);
        }
        #pragma unroll
        for (int o = 16; o; o >>= 1) {
            s1 += __shfl_xor_sync(0xffffffffu, s1, o);
            s2 += __shfl_xor_sync(0xffffffffu, s2, o);
        }
        const float inv1 = 1.0f / s1;
        const float inv2 = 1.0f / s2;
        const float mk = sm_mask[r];
        #pragma unroll
        for (int j = 0; j < 10; j++) {
            probs_t[(goff + lane + j * 32) * TPAD + r] = e1[j] * inv1;
            macc[j] = fmaf(mk, __expf(l[j] - m2) * inv2, macc[j]);
        }
    }
    #pragma unroll
    for (int j = 0; j < 10; j++) wpart[warp][lane + j * 32] = macc[j];
    __syncthreads();

    // ---- per-block marginal partial (fixed order across 4 warps/group) ----
    for (int c = tid; c < GV; c += 256) {
        const int gg = (c >= VPG);
        const int cc = c - gg * VPG;
        g_partial[(size_t)blockIdx.x * GV + c] =
            wpart[gg][cc] + wpart[gg + 2][cc] + wpart[gg + 4][cc] + wpart[gg + 6][cc];
    }

    // ---- P2: cv via packed FFMA2, row pairs; thread = (g, d) ----
    const int g  = tid >> 7;
    const int d  = tid & 127;
    const float* cbg = &cb[(size_t)g * VPG * DPG + d];
    const int pb = g * VPG;

    unsigned long long acc[16];
    #pragma unroll
    for (int rp = 0; rp < 16; rp++) acc[rp] = 0ull;

    #pragma unroll 2
    for (int v = 0; v < VPG; v += 4) {
        unsigned long long cc0 = pack2(cbg[(size_t)(v + 0) * DPG]);
        unsigned long long cc1 = pack2(cbg[(size_t)(v + 1) * DPG]);
        unsigned long long cc2 = pack2(cbg[(size_t)(v + 2) * DPG]);
        unsigned long long cc3 = pack2(cbg[(size_t)(v + 3) * DPG]);
        const float* p0 = &probs_t[(pb + v) * TPAD];
        #pragma unroll
        for (int rp = 0; rp < 16; rp++) {
            unsigned long long a0 = *(const unsigned long long*)(p0 + 2 * rp);
            unsigned long long a1 = *(const unsigned long long*)(p0 + TPAD + 2 * rp);
            unsigned long long a2 = *(const unsigned long long*)(p0 + 2 * TPAD + 2 * rp);
            unsigned long long a3 = *(const unsigned long long*)(p0 + 3 * TPAD + 2 * rp);
            ffma2(acc[rp], a0, cc0);
            ffma2(acc[rp], a1, cc1);
            ffma2(acc[rp], a2, cc2);
            ffma2(acc[rp], a3, cc3);
        }
    }
    #pragma unroll
    for (int rp = 0; rp < 16; rp++) {
        float lo, hi;
        asm("mov.b64 {%0,%1}, %2;" : "=f"(lo), "=f"(hi) : "l"(acc[rp]));
        out[(size_t)(r0 + 2 * rp)     * 256 + g * 128 + d] = lo;
        out[(size_t)(r0 + 2 * rp + 1) * 256 + g * 128 + d] = hi;
    }
}

// ---------------------------------------------------------------------------
__global__ void reduce_marginal_k() {
    const int lane = threadIdx.x & 31;
    const int warp = threadIdx.x >> 5;
    const int c = blockIdx.x * 32 + lane;
    float s = 0.f;
    for (int b = warp; b < NBLK; b += 8)
        s += g_partial[(size_t)b * GV + c];
    __shared__ float red[8][32];
    red[warp][lane] = s;
    __syncthreads();
    if (warp == 0) {
        float v = red[0][lane];
        #pragma unroll
        for (int i = 1; i < 8; i++) v += red[i][lane];
        g_marginal[c] = v;
    }
}

// ---------------------------------------------------------------------------
__global__ void finalize_k(const int* __restrict__ mask,
                           float* __restrict__ out, int out_size) {
    __shared__ double red0[1024], red1[1024];
    __shared__ int    redi[1024];
    const int tid = threadIdx.x;
    const int4* m4 = (const int4*)mask;
    int cnt = 0;
    for (int i = tid; i < M_ROWS / 4; i += 1024) {
        int4 v = m4[i];
        cnt += (v.x != 0) + (v.y != 0) + (v.z != 0) + (v.w != 0);
    }
    redi[tid] = cnt; __syncthreads();
    for (int o = 512; o; o >>= 1) { if (tid < o) redi[tid] += redi[tid + o]; __syncthreads(); }
    const double inv = 1.0 / (double)redi[0];

    double s0 = 0.0, s1 = 0.0;
    for (int c = tid; c < GV; c += 1024) {
        const double m = (double)g_marginal[c] * inv;
        const double tt = m * log(m + 1e-7);
        if (c < VPG) s0 += tt; else s1 += tt;
    }
    red0[tid] = s0; red1[tid] = s1; __syncthreads();
    for (int o = 512; o; o >>= 1) {
        if (tid < o) { red0[tid] += red0[tid + o]; red1[tid] += red1[tid + o]; }
        __syncthreads();
    }
    if (tid == 0) out[out_size - 1] = (float)(exp(-red0[0]) + exp(-red1[0]));
}

// ---------------------------------------------------------------------------
extern "C" void kernel_launch(void* const* d_in, const int* in_sizes, int n_in,
                              void* d_out, int out_size) {
    const float* hs   = (const float*)d_in[0];
    const float* gum  = (const float*)d_in[1];
    const float* W    = (const float*)d_in[2];
    const float* bias = (const float*)d_in[3];
    const float* cb   = (const float*)d_in[4];
    const int*   mask = (const int*)d_in[5];
    float* out = (float*)d_out;

    static int attr_done = 0;
    if (!attr_done) {
        cudaFuncSetAttribute(mma_gemm, cudaFuncAttributeMaxDynamicSharedMemorySize, SMEM_GEMM);
        cudaFuncSetAttribute(fused_k,  cudaFuncAttributeMaxDynamicSharedMemorySize, SMEM_FUSED);
        attr_done = 1;
    }

    conv_w<<<(NDIM * KDIM + 255) / 256, 256>>>(W);
    conv_a<<<(M_ROWS * KDIM / 4) / 256, 256>>>(hs);
    mma_gemm<<<dim3(NDIM / NT, M_ROWS / MT), 256, SMEM_GEMM>>>(bias);
    fused_k<<<NBLK, 256, SMEM_FUSED>>>(gum, cb, mask, out);
    reduce_marginal_k<<<GV / 32, 256>>>();
    finalize_k<<<1, 1024>>>(mask, out, out_size);
}

// round 13
// speedup vs baseline: 1.9739x; 1.0366x over previous
#include <cuda_runtime.h>
#include <cuda_bf16.h>
#include <cstdint>

#define M_ROWS 65536     // B*T
#define KDIM   512       // H
#define NDIM   640       // G*V
#define GV     640
#define VPG    320
#define DPG    128
#define RPB    32
#define NBLK   (M_ROWS / RPB)

// GEMM tiling
#define MT 128
#define NT 128
#define KC 32
#define NKC (KDIM / KC)          // 16
#define APAD 8
#define LDS_STRIDE (KC + APAD)   // 40 ushorts = 80 bytes
#define TILE_U   (MT * LDS_STRIDE)          // 5120 ushorts
#define STAGE_U  (4 * TILE_U)               // 20480 ushorts
#define TILE_B   (TILE_U * 2)               // 10240 bytes
#define STAGE_B  (STAGE_U * 2)              // 40960 bytes
#define SMEM_GEMM (2 * STAGE_B)             // 81920 bytes

// fused_k: transposed probs, padded for 16B-aligned row-quad loads
#define TPAD 36
#define SMEM_FUSED (GV * TPAD * 4)          // 92160 bytes

// Scratch (device globals: allocation-free per harness rules)
__device__ float g_logits[(size_t)M_ROWS * NDIM];            // 160 MB
__device__ float g_partial[(size_t)NBLK * GV];               // 5.2 MB
__device__ float g_marginal[GV];
__device__ unsigned short g_wt_hi[(size_t)NDIM * KDIM];      // W^T hi [640][512]
__device__ unsigned short g_wt_lo[(size_t)NDIM * KDIM];
__device__ unsigned short g_a_hi[(size_t)M_ROWS * KDIM];     // A hi [65536][512]
__device__ unsigned short g_a_lo[(size_t)M_ROWS * KDIM];

// ---------------------------------------------------------------------------
__device__ __forceinline__ void mma_bf16(float* c, const uint32_t* a, const uint32_t* b) {
    asm volatile(
        "mma.sync.aligned.m16n8k16.row.col.f32.bf16.bf16.f32 "
        "{%0,%1,%2,%3}, {%4,%5,%6,%7}, {%8,%9}, {%0,%1,%2,%3};"
        : "+f"(c[0]), "+f"(c[1]), "+f"(c[2]), "+f"(c[3])
        : "r"(a[0]), "r"(a[1]), "r"(a[2]), "r"(a[3]), "r"(b[0]), "r"(b[1]));
}
__device__ __forceinline__ void ldsm4(uint32_t* r, uint32_t addr) {
    asm volatile("ldmatrix.sync.aligned.m8n8.x4.shared.b16 {%0,%1,%2,%3}, [%4];"
        : "=r"(r[0]), "=r"(r[1]), "=r"(r[2]), "=r"(r[3]) : "r"(addr));
}
__device__ __forceinline__ unsigned short bf_hi(float x) {
    return __bfloat16_as_ushort(__float2bfloat16_rn(x));
}
__device__ __forceinline__ unsigned short bf_lo(float x, unsigned short h) {
    return __bfloat16_as_ushort(
        __float2bfloat16_rn(x - __bfloat162float(__ushort_as_bfloat16(h))));
}
__device__ __forceinline__ uint32_t smem_u32(const void* p) {
    uint32_t a;
    asm("{ .reg .u64 t; cvta.to.shared.u64 t, %1; cvt.u32.u64 %0, t; }" : "=r"(a) : "l"(p));
    return a;
}
__device__ __forceinline__ void cp_async16(uint32_t dst, const void* src) {
    asm volatile("cp.async.cg.shared.global [%0], [%1], 16;" :: "r"(dst), "l"(src));
}
#define CP_COMMIT() asm volatile("cp.async.commit_group;" ::: "memory")
#define CP_WAIT(n)  asm volatile("cp.async.wait_group %0;" :: "n"(n) : "memory")

__device__ __forceinline__ unsigned long long pack2(float x) {
    unsigned long long r;
    asm("mov.b64 %0, {%1,%2};" : "=l"(r) : "f"(x), "f"(x));
    return r;
}
__device__ __forceinline__ void ffma2(unsigned long long& d, unsigned long long a,
                                      unsigned long long b) {
    asm("fma.rn.f32x2 %0, %1, %2, %0;" : "+l"(d) : "l"(a), "l"(b));
}

// ---------------------------------------------------------------------------
__global__ void conv_w(const float* __restrict__ W) {
    int idx = blockIdx.x * 256 + threadIdx.x;
    if (idx >= NDIM * KDIM) return;
    int n = idx >> 9, k = idx & 511;
    float x = W[(size_t)k * NDIM + n];
    unsigned short h = bf_hi(x);
    g_wt_hi[idx] = h;
    g_wt_lo[idx] = bf_lo(x, h);
}

__global__ void conv_a(const float* __restrict__ A) {
    size_t i = (size_t)blockIdx.x * 256 + threadIdx.x;
    float4 v = ((const float4*)A)[i];
    ushort4 h, l;
    h.x = bf_hi(v.x); l.x = bf_lo(v.x, h.x);
    h.y = bf_hi(v.y); l.y = bf_lo(v.y, h.y);
    h.z = bf_hi(v.z); l.z = bf_lo(v.z, h.z);
    h.w = bf_hi(v.w); l.w = bf_lo(v.w, h.w);
    ((ushort4*)g_a_hi)[i] = h;
    ((ushort4*)g_a_lo)[i] = l;
}

// ---------------------------------------------------------------------------
// mma_gemm: cp.async double-buffered bf16-split mma.sync GEMM, ldmatrix frags.
// ---------------------------------------------------------------------------
__device__ __forceinline__ void issue_loads(uint32_t sbase, int m0, int n0, int kc, int tid) {
    #pragma unroll
    for (int u = 0; u < 2; ++u) {
        const int idx = u * 256 + tid;                 // 0..511
        const int r = idx >> 2, cc = idx & 3;
        const size_t ga = (size_t)(m0 + r) * KDIM + kc * KC + cc * 8;
        const size_t gb = (size_t)(n0 + r) * KDIM + kc * KC + cc * 8;
        const uint32_t so = (uint32_t)(r * LDS_STRIDE + cc * 8) * 2;  // bytes
        cp_async16(sbase + so,              g_a_hi  + ga);
        cp_async16(sbase + TILE_B + so,     g_a_lo  + ga);
        cp_async16(sbase + 2 * TILE_B + so, g_wt_hi + gb);
        cp_async16(sbase + 3 * TILE_B + so, g_wt_lo + gb);
    }
}

__global__ void __launch_bounds__(256, 2)
mma_gemm(const float* __restrict__ bias) {
    extern __shared__ unsigned short smg[];
    const uint32_t sb = smem_u32(smg);

    const int tid  = threadIdx.x;
    const int wid  = tid >> 5;
    const int lane = tid & 31;
    const int g    = lane >> 2;
    const int t    = lane & 3;
    const int n0   = blockIdx.x * NT;
    const int m0   = blockIdx.y * MT;
    const int wm   = (wid & 3) * 32;
    const int wn   = (wid >> 2) * 64;

    // ldmatrix per-lane offsets (ushort units)
    const uint32_t a_off = (uint32_t)((wm + (lane & 15)) * LDS_STRIDE + ((lane >> 4) << 3));
    const uint32_t b_off = (uint32_t)((wn + ((lane >> 4) << 3) + (lane & 7)) * LDS_STRIDE
                                      + (((lane >> 3) & 1) << 3));

    float c[2][8][4];
    #pragma unroll
    for (int i = 0; i < 2; i++)
        #pragma unroll
        for (int j = 0; j < 8; j++)
            #pragma unroll
            for (int q = 0; q < 4; q++) c[i][j][q] = 0.f;

    issue_loads(sb, m0, n0, 0, tid);
    CP_COMMIT();

    for (int kc = 0; kc < NKC; ++kc) {
        if (kc + 1 < NKC) {
            issue_loads(sb + ((kc + 1) & 1) * STAGE_B, m0, n0, kc + 1, tid);
            CP_COMMIT();
            CP_WAIT(1);
        } else {
            CP_WAIT(0);
        }
        __syncthreads();

        const uint32_t stage = sb + (kc & 1) * STAGE_B;
        const uint32_t aHi = stage + a_off * 2;
        const uint32_t aLo = aHi + TILE_B;
        const uint32_t bHi = stage + 2 * TILE_B + b_off * 2;
        const uint32_t bLo = bHi + TILE_B;

        #pragma unroll
        for (int ks = 0; ks < 2; ++ks) {
            const uint32_t kbb = ks * 32;          // 16 ushorts = 32 bytes
            uint32_t ah[2][4], al[2][4];
            #pragma unroll
            for (int i = 0; i < 2; ++i) {
                ldsm4(ah[i], aHi + i * (16 * LDS_STRIDE * 2) + kbb);
                ldsm4(al[i], aLo + i * (16 * LDS_STRIDE * 2) + kbb);
            }
            #pragma unroll
            for (int jp = 0; jp < 4; ++jp) {
                uint32_t bh[4], bl[4];
                ldsm4(bh, bHi + jp * (16 * LDS_STRIDE * 2) + kbb);
                ldsm4(bl, bLo + jp * (16 * LDS_STRIDE * 2) + kbb);
                #pragma unroll
                for (int jj = 0; jj < 2; ++jj) {
                    #pragma unroll
                    for (int i = 0; i < 2; ++i) {
                        mma_bf16(c[i][2 * jp + jj], ah[i], bh + 2 * jj);
                        mma_bf16(c[i][2 * jp + jj], al[i], bh + 2 * jj);
                        mma_bf16(c[i][2 * jp + jj], ah[i], bl + 2 * jj);
                    }
                }
            }
        }
        __syncthreads();
    }

    #pragma unroll
    for (int j = 0; j < 8; ++j) {
        const int col = n0 + wn + j * 8 + 2 * t;
        const float2 bv = *(const float2*)&bias[col];
        #pragma unroll
        for (int i = 0; i < 2; ++i) {
            const int row = m0 + wm + i * 16 + g;
            float2 v0 = { c[i][j][0] + bv.x, c[i][j][1] + bv.y };
            float2 v1 = { c[i][j][2] + bv.x, c[i][j][3] + bv.y };
            *(float2*)&g_logits[(size_t)row * NDIM + col]       = v0;
            *(float2*)&g_logits[(size_t)(row + 8) * NDIM + col] = v1;
        }
    }
}

// ---------------------------------------------------------------------------
// fused_k: gumbel-softmax (transposed probs) + in-register soft-marginal +
//          FFMA2 codebook einsum with LDS.128 row-quad loads.
// ---------------------------------------------------------------------------
__global__ void fused_k(const float* __restrict__ gumbels,
                        const float* __restrict__ cb,
                        const int* __restrict__ mask,
                        float* __restrict__ out) {
    extern __shared__ float probs_t[];        // [GV][TPAD]
    __shared__ float wpart[8][VPG];
    __shared__ float sm_mask[RPB];

    const int tid  = threadIdx.x;
    const int lane = tid & 31;
    const int warp = tid >> 5;
    const int r0   = blockIdx.x * RPB;

    if (tid < RPB) sm_mask[tid] = mask[r0 + tid] ? 1.0f : 0.0f;
    __syncthreads();

    // ---- P1: per (row, group) softmaxes; warp owns group g = warp&1 ----
    const int g1    = warp & 1;
    const int rbase = warp >> 1;
    const int goff  = g1 * VPG;
    float macc[10];
    #pragma unroll
    for (int j = 0; j < 10; j++) macc[j] = 0.f;

    #pragma unroll 1
    for (int k = 0; k < 8; ++k) {
        const int r = rbase + 4 * k;
        const float* lrow = &g_logits[(size_t)(r0 + r) * NDIM + goff];
        const float* grow = &gumbels [(size_t)(r0 + r) * NDIM + goff];
        float l[10], x1[10];
        float m1 = -1e30f, m2 = -1e30f;
        #pragma unroll
        for (int j = 0; j < 10; j++) {
            const int v = lane + j * 32;
            l[j]  = lrow[v];
            x1[j] = (l[j] + grow[v]) * 0.5f;
            m1 = fmaxf(m1, x1[j]); m2 = fmaxf(m2, l[j]);
        }
        #pragma unroll
        for (int o = 16; o; o >>= 1) {
            m1 = fmaxf(m1, __shfl_xor_sync(0xffffffffu, m1, o));
            m2 = fmaxf(m2, __shfl_xor_sync(0xffffffffu, m2, o));
        }
        float e1[10], s1 = 0.f, s2 = 0.f;
        #pragma unroll
        for (int j = 0; j < 10; j++) {
            e1[j] = __expf(x1[j] - m1); s1 += e1[j];
            s2 += __expf(l[j] - m2);
        }
        #pragma unroll
        for (int o = 16; o; o >>= 1) {
            s1 += __shfl_xor_sync(0xffffffffu, s1, o);
            s2 += __shfl_xor_sync(0xffffffffu, s2, o);
        }
        const float inv1 = 1.0f / s1;
        const float inv2 = 1.0f / s2;
        const float mk = sm_mask[r];
        #pragma unroll
        for (int j = 0; j < 10; j++) {
            probs_t[(goff + lane + j * 32) * TPAD + r] = e1[j] * inv1;
            macc[j] = fmaf(mk, __expf(l[j] - m2) * inv2, macc[j]);
        }
    }
    #pragma unroll
    for (int j = 0; j < 10; j++) wpart[warp][lane + j * 32] = macc[j];
    __syncthreads();

    // ---- per-block marginal partial (fixed order across 4 warps/group) ----
    for (int c = tid; c < GV; c += 256) {
        const int gg = (c >= VPG);
        const int cc = c - gg * VPG;
        g_partial[(size_t)blockIdx.x * GV + c] =
            wpart[gg][cc] + wpart[gg + 2][cc] + wpart[gg + 4][cc] + wpart[gg + 6][cc];
    }

    // ---- P2: cv via packed FFMA2; LDS.128 loads 4 rows at a time ----
    const int g  = tid >> 7;
    const int d  = tid & 127;
    const float* cbg = &cb[(size_t)g * VPG * DPG + d];
    const int pb = g * VPG;

    unsigned long long acc[16];
    #pragma unroll
    for (int rp = 0; rp < 16; rp++) acc[rp] = 0ull;

    #pragma unroll 2
    for (int v = 0; v < VPG; v += 4) {
        unsigned long long cc0 = pack2(cbg[(size_t)(v + 0) * DPG]);
        unsigned long long cc1 = pack2(cbg[(size_t)(v + 1) * DPG]);
        unsigned long long cc2 = pack2(cbg[(size_t)(v + 2) * DPG]);
        unsigned long long cc3 = pack2(cbg[(size_t)(v + 3) * DPG]);
        const float* p0 = &probs_t[(pb + v) * TPAD];
        #pragma unroll
        for (int q = 0; q < 8; ++q) {
            ulonglong2 a0 = *(const ulonglong2*)(p0 + 4 * q);
            ulonglong2 a1 = *(const ulonglong2*)(p0 + TPAD + 4 * q);
            ulonglong2 a2 = *(const ulonglong2*)(p0 + 2 * TPAD + 4 * q);
            ulonglong2 a3 = *(const ulonglong2*)(p0 + 3 * TPAD + 4 * q);
            ffma2(acc[2 * q],     a0.x, cc0);
            ffma2(acc[2 * q + 1], a0.y, cc0);
            ffma2(acc[2 * q],     a1.x, cc1);
            ffma2(acc[2 * q + 1], a1.y, cc1);
            ffma2(acc[2 * q],     a2.x, cc2);
            ffma2(acc[2 * q + 1], a2.y, cc2);
            ffma2(acc[2 * q],     a3.x, cc3);
            ffma2(acc[2 * q + 1], a3.y, cc3);
        }
    }
    #pragma unroll
    for (int rp = 0; rp < 16; rp++) {
        float lo, hi;
        asm("mov.b64 {%0,%1}, %2;" : "=f"(lo), "=f"(hi) : "l"(acc[rp]));
        out[(size_t)(r0 + 2 * rp)     * 256 + g * 128 + d] = lo;
        out[(size_t)(r0 + 2 * rp + 1) * 256 + g * 128 + d] = hi;
    }
}

// ---------------------------------------------------------------------------
__global__ void reduce_marginal_k() {
    const int lane = threadIdx.x & 31;
    const int warp = threadIdx.x >> 5;
    const int c = blockIdx.x * 32 + lane;
    float s = 0.f;
    for (int b = warp; b < NBLK; b += 8)
        s += g_partial[(size_t)b * GV + c];
    __shared__ float red[8][32];
    red[warp][lane] = s;
    __syncthreads();
    if (warp == 0) {
        float v = red[0][lane];
        #pragma unroll
        for (int i = 1; i < 8; i++) v += red[i][lane];
        g_marginal[c] = v;
    }
}

// ---------------------------------------------------------------------------
__global__ void finalize_k(const int* __restrict__ mask,
                           float* __restrict__ out, int out_size) {
    __shared__ double red0[1024], red1[1024];
    __shared__ int    redi[1024];
    const int tid = threadIdx.x;
    const int4* m4 = (const int4*)mask;
    int cnt = 0;
    for (int i = tid; i < M_ROWS / 4; i += 1024) {
        int4 v = m4[i];
        cnt += (v.x != 0) + (v.y != 0) + (v.z != 0) + (v.w != 0);
    }
    redi[tid] = cnt; __syncthreads();
    for (int o = 512; o; o >>= 1) { if (tid < o) redi[tid] += redi[tid + o]; __syncthreads(); }
    const double inv = 1.0 / (double)redi[0];

    double s0 = 0.0, s1 = 0.0;
    for (int c = tid; c < GV; c += 1024) {
        const double m = (double)g_marginal[c] * inv;
        const double tt = m * log(m + 1e-7);
        if (c < VPG) s0 += tt; else s1 += tt;
    }
    red0[tid] = s0; red1[tid] = s1; __syncthreads();
    for (int o = 512; o; o >>= 1) {
        if (tid < o) { red0[tid] += red0[tid + o]; red1[tid] += red1[tid + o]; }
        __syncthreads();
    }
    if (tid == 0) out[out_size - 1] = (float)(exp(-red0[0]) + exp(-red1[0]));
}

// ---------------------------------------------------------------------------
extern "C" void kernel_launch(void* const* d_in, const int* in_sizes, int n_in,
                              void* d_out, int out_size) {
    const float* hs   = (const float*)d_in[0];
    const float* gum  = (const float*)d_in[1];
    const float* W    = (const float*)d_in[2];
    const float* bias = (const float*)d_in[3];
    const float* cb   = (const float*)d_in[4];
    const int*   mask = (const int*)d_in[5];
    float* out = (float*)d_out;

    static int attr_done = 0;
    if (!attr_done) {
        cudaFuncSetAttribute(mma_gemm, cudaFuncAttributeMaxDynamicSharedMemorySize, SMEM_GEMM);
        cudaFuncSetAttribute(fused_k,  cudaFuncAttributeMaxDynamicSharedMemorySize, SMEM_FUSED);
        attr_done = 1;
    }

    conv_w<<<(NDIM * KDIM + 255) / 256, 256>>>(W);
    conv_a<<<(M_ROWS * KDIM / 4) / 256, 256>>>(hs);
    mma_gemm<<<dim3(NDIM / NT, M_ROWS / MT), 256, SMEM_GEMM>>>(bias);
    fused_k<<<NBLK, 256, SMEM_FUSED>>>(gum, cb, mask, out);
    reduce_marginal_k<<<GV / 32, 256>>>();
    finalize_k<<<1, 1024>>>(mask, out, out_size);
}